// round 9
// baseline (speedup 1.0000x reference)
#include <cuda_runtime.h>
#include <cuda_bf16.h>

// PCEN via exact parallel linear-recurrence scan (constant per-row decay a=1-s).
// R9: R8 instruction diet (n-space recurrence, seed folded into w00, MUFU lane
// powers) + FIXED chunk-1 seed: warp 31 has 24 inactive lanes, so n[3999] is
// reconstructed as D^8 * (state entering warp 31) + thread999's local partial
// (the R7 method), not shfl(total,31) which picks up a^96 of phantom decay.

#define TT    8000
#define HALF  4000
#define EPT   4
#define NTH   1024
#define NWARP (NTH/32)
#define ALPHA_C 0.98f
#define DELTA_C 2.0f
#define EPS_C   1e-6f
#define SQRT_DELTA 1.41421356237f
#define LOG2E 1.44269504089f

__device__ __forceinline__ float f_lg2(float x) {
    float r; asm("lg2.approx.f32 %0, %1;" : "=f"(r) : "f"(x)); return r;
}
__device__ __forceinline__ float f_ex2(float x) {
    float r; asm("ex2.approx.f32 %0, %1;" : "=f"(r) : "f"(x)); return r;
}
__device__ __forceinline__ float f_sqrt(float x) {
    float r; asm("sqrt.approx.f32 %0, %1;" : "=f"(r) : "f"(x)); return r;
}
__device__ __forceinline__ float f_rcp(float x) {
    float r; asm("rcp.approx.f32 %0, %1;" : "=f"(r) : "f"(x)); return r;
}

__global__ __launch_bounds__(NTH, 2)
void pcen_kernel(const float* __restrict__ x,
                 const float* __restrict__ log_s,
                 float* __restrict__ out,
                 int F)
{
    const int row = blockIdx.x;
    const float s = f_ex2(LOG2E * __ldg(log_s + (row % F)));
    const float a = 1.0f - s;

    const float* xr   = x   + (long long)row * TT;
    float*       orow = out + (long long)row * TT;

    const int t    = threadIdx.x;
    const bool active = (t < HALF / EPT);       // threads 0..999
    const int lane = t & 31;
    const int wid  = t >> 5;

    __shared__ float tot0[NWARP], tot1[NWARP];
    __shared__ float val999sh;

    // ---- perfectly coalesced loads: 2x LDG.128 ----
    float c0[EPT], c1[EPT];
    if (active) {
        float4 v0 = *(const float4*)(xr + 4 * t);
        float4 v1 = *(const float4*)(xr + HALF + 4 * t);
        c0[0]=v0.x; c0[1]=v0.y; c0[2]=v0.z; c0[3]=v0.w;
        c1[0]=v1.x; c1[1]=v1.y; c1[2]=v1.z; c1[3]=v1.w;
    } else {
        #pragma unroll
        for (int i = 0; i < EPT; i++) { c0[i] = 0.0f; c1[i] = 0.0f; }
    }

    // init condition m[-1]=x0 folded into thread0's first n-space weight:
    // n[0] must equal x0/s  ->  w00 = x0 * rcp(s) for t==0 only.
    const float w00 = (t == 0) ? c0[0] * f_rcp(s) : c0[0];

    // ---- pass 1: zero-init local n-space scans ----
    float Fv0 = w00, Fv1 = c1[0];
    #pragma unroll
    for (int i = 1; i < EPT; i++) {
        Fv0 = fmaf(a, Fv0, c0[i]);
        Fv1 = fmaf(a, Fv1, c1[i]);
    }

    const float lga = f_lg2(a);
    float a2 = a * a;
    const float D = a2 * a2;                    // a^4 exact

    // ---- level 2: fused warp scan ----
    float v0 = Fv0, v1 = Fv1;
    float pw = D;
    #pragma unroll
    for (int off = 1; off < 32; off <<= 1) {
        float u0 = __shfl_up_sync(0xFFFFFFFFu, v0, off);
        float u1 = __shfl_up_sync(0xFFFFFFFFu, v1, off);
        if (lane >= off) { v0 = fmaf(pw, u0, v0); v1 = fmaf(pw, u1, v1); }
        pw *= pw;
    }
    const float Dw = pw;                        // D^32 = a^128
    const float pl = f_ex2((float)lane * (4.0f * lga));     // D^lane

    if (lane == 31) { tot0[wid] = v0; tot1[wid] = v1; }
    if (t == 999)   val999sh = v0;              // inclusive partial at seg 999

    float vex0 = __shfl_up_sync(0xFFFFFFFFu, v0, 1);
    float vex1 = __shfl_up_sync(0xFFFFFFFFu, v1, 1);
    if (lane == 0) { vex0 = 0.0f; vex1 = 0.0f; }

    __syncthreads();

    // ---- level 3: every warp redundantly scans the 32 warp totals ----
    float w0 = tot0[lane], w1 = tot1[lane];
    float q  = Dw;
    #pragma unroll
    for (int off = 1; off < 32; off <<= 1) {
        float u0 = __shfl_up_sync(0xFFFFFFFFu, w0, off);
        float u1 = __shfl_up_sync(0xFFFFFFFFu, w1, off);
        if (lane >= off) { w0 = fmaf(q, u0, w0); w1 = fmaf(q, u1, w1); }
        q *= q;
    }

    // chunk-1 seed: S0 = n[3999] = D^8 * (state entering warp 31) + val999.
    // (warp 31 holds only 8 active segments; lanes 8..31 are phantom zeros)
    float e31 = __shfl_sync(0xFFFFFFFFu, w0, 30);   // inclusive @ lane 30
    float D2 = D * D, D4 = D2 * D2, D8 = D4 * D4;   // a^32
    const float S0 = fmaf(D8, e31, val999sh);

    // exclusive level-3 prefixes for this warp
    const int src = (wid == 0) ? 0 : (wid - 1);
    float ex0 = __shfl_sync(0xFFFFFFFFu, w0, src);
    float ex1 = __shfl_sync(0xFFFFFFFFu, w1, src);
    if (wid == 0) { ex0 = 0.0f; ex1 = 0.0f; }
    const float plw = f_ex2((float)wid * (128.0f * lga));   // Dw^wid (ex2(0)=1)

    const float carry0 = fmaf(pl, ex0, vex0);
    const float carry1 = fmaf(pl, fmaf(plw, S0, ex1), vex1);

    // ---- pass 2: replay in n-space + epilogue, coalesced stores ----
    if (active) {
        float n0 = carry0, n1 = carry1;
        #pragma unroll
        for (int i = 0; i < EPT; i++) {
            n0 = fmaf(a, n0, (i == 0) ? w00 : c0[i]);
            n1 = fmaf(a, n1, c1[i]);
            float l0 = f_lg2(fmaf(s, n0, EPS_C));   // lg2(eps + m)
            float l1 = f_lg2(fmaf(s, n1, EPS_C));
            float i0 = f_ex2(-ALPHA_C * l0);
            float i1 = f_ex2(-ALPHA_C * l1);
            float u0 = fmaf(c0[i], i0, DELTA_C);
            float u1 = fmaf(c1[i], i1, DELTA_C);
            c0[i] = f_sqrt(u0) - SQRT_DELTA;
            c1[i] = f_sqrt(u1) - SQRT_DELTA;
        }
        *(float4*)(orow + 4 * t)        = make_float4(c0[0], c0[1], c0[2], c0[3]);
        *(float4*)(orow + HALF + 4 * t) = make_float4(c1[0], c1[1], c1[2], c1[3]);
    }
}

extern "C" void kernel_launch(void* const* d_in, const int* in_sizes, int n_in,
                              void* d_out, int out_size)
{
    int xi = 0, si = 1;
    if (n_in >= 2 && in_sizes[0] < in_sizes[1]) { xi = 1; si = 0; }

    const float* x     = (const float*)d_in[xi];
    const float* log_s = (const float*)d_in[si];
    float*       out   = (float*)d_out;

    const int F    = in_sizes[si];           // 128
    const int rows = in_sizes[xi] / TT;      // B*F = 4096

    pcen_kernel<<<rows, NTH>>>(x, log_s, out, F);
}

// round 10
// speedup vs baseline: 1.0545x; 1.0545x over previous
#include <cuda_runtime.h>
#include <cuda_bf16.h>
#include <cstdint>

// PCEN via exact parallel linear-recurrence scan (constant per-row decay a=1-s).
// R10: persistent kernel (grid = 2*148 CTAs, each loops over ~14 rows) with
// cp.async double-buffered smem prefetch: row i+1 streams into the idle buffer
// while row i is scanned. Removes all wave transitions and hides DRAM latency
// behind compute. Scan math identical to R9 (n-space, seed folded into w00,
// MUFU lane powers, warp31-aware chunk-1 seed reconstruction).

#define TT    8000
#define HALF  4000
#define NTH   1024
#define NWARP (NTH/32)
#define GRID_MAX 296            // 2 CTAs/SM * 148 SMs
#define ALPHA_C 0.98f
#define DELTA_C 2.0f
#define EPS_C   1e-6f
#define SQRT_DELTA 1.41421356237f
#define LOG2E 1.44269504089f

// dynamic smem layout (floats): buf0[8000] buf1[8000] tot0[32] tot1[32] v999
#define OFF_TOT0 (2*TT)
#define OFF_TOT1 (2*TT + 32)
#define OFF_V999 (2*TT + 64)
#define SMEM_FLOATS (2*TT + 80)

__device__ __forceinline__ float f_lg2(float x) {
    float r; asm("lg2.approx.f32 %0, %1;" : "=f"(r) : "f"(x)); return r;
}
__device__ __forceinline__ float f_ex2(float x) {
    float r; asm("ex2.approx.f32 %0, %1;" : "=f"(r) : "f"(x)); return r;
}
__device__ __forceinline__ float f_sqrt(float x) {
    float r; asm("sqrt.approx.f32 %0, %1;" : "=f"(r) : "f"(x)); return r;
}
__device__ __forceinline__ float f_rcp(float x) {
    float r; asm("rcp.approx.f32 %0, %1;" : "=f"(r) : "f"(x)); return r;
}

__device__ __forceinline__ void cp16(uint32_t saddr, const float* g) {
    asm volatile("cp.async.cg.shared.global [%0], [%1], 16;"
                 :: "r"(saddr), "l"(g));
}

__global__ __launch_bounds__(NTH, 2)
void pcen_kernel(const float* __restrict__ x,
                 const float* __restrict__ log_s,
                 float* __restrict__ out,
                 int F, int rows)
{
    extern __shared__ float smem[];

    const int t    = threadIdx.x;
    const bool active = (t < HALF / 4);        // threads 0..999
    const int lane = t & 31;
    const int wid  = t >> 5;
    const int stride = gridDim.x;

    const uint32_t sbase = (uint32_t)__cvta_generic_to_shared(smem);

    // ---- prologue: prefetch first row into buf0 ----
    int row = blockIdx.x;
    if (row < rows && active) {
        const float* xr = x + (long long)row * TT;
        cp16(sbase + 4u * (4 * t),        xr + 4 * t);
        cp16(sbase + 4u * (HALF + 4 * t), xr + HALF + 4 * t);
    }
    asm volatile("cp.async.commit_group;");

    int bufsel = 0;
    for (; row < rows; row += stride) {
        // ---- issue prefetch of next row into the other buffer ----
        int nrow = row + stride; if (nrow >= rows) nrow = row;   // benign clamp
        {
            const float* xn = x + (long long)nrow * TT;
            uint32_t nb = sbase + 4u * (uint32_t)((bufsel ^ 1) * TT);
            if (active) {
                cp16(nb + 4u * (4 * t),        xn + 4 * t);
                cp16(nb + 4u * (HALF + 4 * t), xn + HALF + 4 * t);
            }
        }
        asm volatile("cp.async.commit_group;");
        asm volatile("cp.async.wait_group 1;");   // current row's copies done
        __syncthreads();                          // bar A: buffer visible to all

        // ---- per-row constants ----
        const float s = f_ex2(LOG2E * __ldg(log_s + (row % F)));
        const float a = 1.0f - s;
        const float lga = f_lg2(a);
        float a2 = a * a;
        const float D = a2 * a2;                  // a^4 exact

        const float* buf = smem + bufsel * TT;
        float c0[4], c1[4];
        if (active) {
            float4 v0 = *(const float4*)(buf + 4 * t);
            float4 v1 = *(const float4*)(buf + HALF + 4 * t);
            c0[0]=v0.x; c0[1]=v0.y; c0[2]=v0.z; c0[3]=v0.w;
            c1[0]=v1.x; c1[1]=v1.y; c1[2]=v1.z; c1[3]=v1.w;
        } else {
            #pragma unroll
            for (int i = 0; i < 4; i++) { c0[i] = 0.0f; c1[i] = 0.0f; }
        }

        // init condition folded: n[0] = x0/s -> w00 = x0 * rcp(s) on thread 0
        const float w00 = (t == 0) ? c0[0] * f_rcp(s) : c0[0];

        // ---- pass 1: local n-space scans ----
        float Fv0 = w00, Fv1 = c1[0];
        #pragma unroll
        for (int i = 1; i < 4; i++) {
            Fv0 = fmaf(a, Fv0, c0[i]);
            Fv1 = fmaf(a, Fv1, c1[i]);
        }

        // ---- level 2: fused warp scan ----
        float v0 = Fv0, v1 = Fv1;
        float pw = D;
        #pragma unroll
        for (int off = 1; off < 32; off <<= 1) {
            float u0 = __shfl_up_sync(0xFFFFFFFFu, v0, off);
            float u1 = __shfl_up_sync(0xFFFFFFFFu, v1, off);
            if (lane >= off) { v0 = fmaf(pw, u0, v0); v1 = fmaf(pw, u1, v1); }
            pw *= pw;
        }
        const float Dw = pw;                      // a^128
        const float pl = f_ex2((float)lane * (4.0f * lga));   // D^lane

        if (lane == 31) { smem[OFF_TOT0 + wid] = v0; smem[OFF_TOT1 + wid] = v1; }
        if (t == 999)   smem[OFF_V999] = v0;

        float vex0 = __shfl_up_sync(0xFFFFFFFFu, v0, 1);
        float vex1 = __shfl_up_sync(0xFFFFFFFFu, v1, 1);
        if (lane == 0) { vex0 = 0.0f; vex1 = 0.0f; }

        __syncthreads();                          // bar B (also pipeline fence)

        // ---- level 3: every warp redundantly scans the 32 warp totals ----
        float w0 = smem[OFF_TOT0 + lane], w1 = smem[OFF_TOT1 + lane];
        float q  = Dw;
        #pragma unroll
        for (int off = 1; off < 32; off <<= 1) {
            float u0 = __shfl_up_sync(0xFFFFFFFFu, w0, off);
            float u1 = __shfl_up_sync(0xFFFFFFFFu, w1, off);
            if (lane >= off) { w0 = fmaf(q, u0, w0); w1 = fmaf(q, u1, w1); }
            q *= q;
        }

        // chunk-1 seed: n[3999] = D^8 * (state entering warp 31) + val999
        float e31 = __shfl_sync(0xFFFFFFFFu, w0, 30);
        float D2 = D * D, D4 = D2 * D2, D8 = D4 * D4;   // a^32
        const float S0 = fmaf(D8, e31, smem[OFF_V999]);

        const int src = (wid == 0) ? 0 : (wid - 1);
        float ex0 = __shfl_sync(0xFFFFFFFFu, w0, src);
        float ex1 = __shfl_sync(0xFFFFFFFFu, w1, src);
        if (wid == 0) { ex0 = 0.0f; ex1 = 0.0f; }
        const float plw = f_ex2((float)wid * (128.0f * lga));  // Dw^wid

        const float carry0 = fmaf(pl, ex0, vex0);
        const float carry1 = fmaf(pl, fmaf(plw, S0, ex1), vex1);

        // ---- pass 2: replay + epilogue, coalesced stores ----
        if (active) {
            float* orow = out + (long long)row * TT;
            float n0 = carry0, n1 = carry1;
            #pragma unroll
            for (int i = 0; i < 4; i++) {
                n0 = fmaf(a, n0, (i == 0) ? w00 : c0[i]);
                n1 = fmaf(a, n1, c1[i]);
                float l0 = f_lg2(fmaf(s, n0, EPS_C));
                float l1 = f_lg2(fmaf(s, n1, EPS_C));
                float i0 = f_ex2(-ALPHA_C * l0);
                float i1 = f_ex2(-ALPHA_C * l1);
                float u0 = fmaf(c0[i], i0, DELTA_C);
                float u1 = fmaf(c1[i], i1, DELTA_C);
                c0[i] = f_sqrt(u0) - SQRT_DELTA;
                c1[i] = f_sqrt(u1) - SQRT_DELTA;
            }
            *(float4*)(orow + 4 * t)        = make_float4(c0[0], c0[1], c0[2], c0[3]);
            *(float4*)(orow + HALF + 4 * t) = make_float4(c1[0], c1[1], c1[2], c1[3]);
        }

        bufsel ^= 1;
    }
}

extern "C" void kernel_launch(void* const* d_in, const int* in_sizes, int n_in,
                              void* d_out, int out_size)
{
    int xi = 0, si = 1;
    if (n_in >= 2 && in_sizes[0] < in_sizes[1]) { xi = 1; si = 0; }

    const float* x     = (const float*)d_in[xi];
    const float* log_s = (const float*)d_in[si];
    float*       out   = (float*)d_out;

    const int F    = in_sizes[si];           // 128
    const int rows = in_sizes[xi] / TT;      // B*F = 4096

    const int smem_bytes = SMEM_FLOATS * (int)sizeof(float);   // ~64.3 KB
    cudaFuncSetAttribute(pcen_kernel,
                         cudaFuncAttributeMaxDynamicSharedMemorySize, smem_bytes);

    int grid = GRID_MAX; if (grid > rows) grid = rows;
    pcen_kernel<<<grid, NTH, smem_bytes>>>(x, log_s, out, F, rows);
}

// round 11
// speedup vs baseline: 1.0951x; 1.0385x over previous
#include <cuda_runtime.h>
#include <cuda_bf16.h>
#include <cstdint>

// PCEN via exact parallel linear-recurrence scan (constant per-row decay a=1-s).
// R11: persistent + cp.async double-buffer (R10) with:
//  - ONE barrier per row: cp.async data is thread-private (each thread reads
//    only bytes it copied; wait_group gives self-visibility) -> bar A removed.
//    Scratch (warp totals) double-buffered to kill the cross-iteration WAR.
//  - log_s prefetched one row ahead (s gates the whole row's dependency tree).
//  - incremental f (no % in loop) and running 64-bit row offset (no row*TT).
//  - prefetch issued right after current buffer is consumed.

#define TT    8000
#define HALF  4000
#define NTH   1024
#define NWARP (NTH/32)
#define GRID_MAX 296            // 2 CTAs/SM * 148 SMs
#define ALPHA_C 0.98f
#define DELTA_C 2.0f
#define EPS_C   1e-6f
#define SQRT_DELTA 1.41421356237f
#define LOG2E 1.44269504089f

// dynamic smem (floats): buf0[8000] buf1[8000] scr0[66] scr1[66]
#define OFF_SCR   (2*TT)
#define SCR_SIZE  66
#define SMEM_FLOATS (2*TT + 2*SCR_SIZE)

__device__ __forceinline__ float f_lg2(float x) {
    float r; asm("lg2.approx.f32 %0, %1;" : "=f"(r) : "f"(x)); return r;
}
__device__ __forceinline__ float f_ex2(float x) {
    float r; asm("ex2.approx.f32 %0, %1;" : "=f"(r) : "f"(x)); return r;
}
__device__ __forceinline__ float f_sqrt(float x) {
    float r; asm("sqrt.approx.f32 %0, %1;" : "=f"(r) : "f"(x)); return r;
}
__device__ __forceinline__ float f_rcp(float x) {
    float r; asm("rcp.approx.f32 %0, %1;" : "=f"(r) : "f"(x)); return r;
}
__device__ __forceinline__ void cp16(uint32_t saddr, const float* g) {
    asm volatile("cp.async.cg.shared.global [%0], [%1], 16;"
                 :: "r"(saddr), "l"(g));
}

__global__ __launch_bounds__(NTH, 2)
void pcen_kernel(const float* __restrict__ x,
                 const float* __restrict__ log_s,
                 float* __restrict__ out,
                 int F, int rows)
{
    extern __shared__ float smem[];

    const int t    = threadIdx.x;
    const bool active = (t < HALF / 4);        // threads 0..999
    const int lane = t & 31;
    const int wid  = t >> 5;
    const int stride = gridDim.x;

    const uint32_t sbase = (uint32_t)__cvta_generic_to_shared(smem);
    const uint32_t sA = sbase + 16u * (uint32_t)t;            // buf slot A
    const uint32_t sB = sA + 4u * HALF;                       // buf slot B
    const float flane4   = (float)lane * 4.0f;
    const float fwid128  = (float)wid * 128.0f;

    int row = blockIdx.x;
    long long rowoff = (long long)row * TT;
    const long long rowstep = (long long)stride * TT;
    int f = row % F;                                          // once
    const int fstep = stride % F;

    // prefetch s for the first row + first row data into buf0
    float s_raw = (row < rows) ? __ldg(log_s + f) : 0.0f;
    if (row < rows && active) {
        cp16(sA, x + rowoff + 4 * t);
        cp16(sB, x + rowoff + HALF + 4 * t);
    }
    asm volatile("cp.async.commit_group;");

    int bufsel = 0;
    while (row < rows) {
        // ---- wait for this row's copies (self-visibility; no barrier) ----
        asm volatile("cp.async.wait_group 0;");

        const uint32_t bofs = (uint32_t)bufsel * (4u * TT);
        float c0[4], c1[4];
        if (active) {
            float4 v0, v1;
            asm volatile("ld.shared.v4.f32 {%0,%1,%2,%3}, [%4];"
                         : "=f"(v0.x), "=f"(v0.y), "=f"(v0.z), "=f"(v0.w)
                         : "r"(sA + bofs));
            asm volatile("ld.shared.v4.f32 {%0,%1,%2,%3}, [%4];"
                         : "=f"(v1.x), "=f"(v1.y), "=f"(v1.z), "=f"(v1.w)
                         : "r"(sB + bofs));
            c0[0]=v0.x; c0[1]=v0.y; c0[2]=v0.z; c0[3]=v0.w;
            c1[0]=v1.x; c1[1]=v1.y; c1[2]=v1.z; c1[3]=v1.w;
        } else {
            #pragma unroll
            for (int i = 0; i < 4; i++) { c0[i] = 0.0f; c1[i] = 0.0f; }
        }

        // ---- buffer free: issue next row's prefetch immediately ----
        const int nrow = row + stride;
        const long long nrowoff = rowoff + rowstep;
        int nf = f + fstep; if (nf >= F) nf -= F;
        float s_next = 0.0f;
        {
            const uint32_t nofs = (uint32_t)(bufsel ^ 1) * (4u * TT);
            if (nrow < rows) {
                s_next = __ldg(log_s + nf);
                if (active) {
                    cp16(sA + nofs, x + nrowoff + 4 * t);
                    cp16(sB + nofs, x + nrowoff + HALF + 4 * t);
                }
            }
        }
        asm volatile("cp.async.commit_group;");

        // ---- per-row constants ----
        const float s = f_ex2(LOG2E * s_raw);
        const float a = 1.0f - s;
        const float lga = f_lg2(a);
        float a2 = a * a;
        const float D = a2 * a2;                  // a^4 exact

        // init condition folded: n[0] = x0/s -> w00 = x0 * rcp(s) on thread 0
        const float w00 = (t == 0) ? c0[0] * f_rcp(s) : c0[0];

        // ---- pass 1: local n-space scans ----
        float Fv0 = w00, Fv1 = c1[0];
        #pragma unroll
        for (int i = 1; i < 4; i++) {
            Fv0 = fmaf(a, Fv0, c0[i]);
            Fv1 = fmaf(a, Fv1, c1[i]);
        }

        // ---- level 2: fused warp scan ----
        float v0 = Fv0, v1 = Fv1;
        float pw = D;
        #pragma unroll
        for (int off = 1; off < 32; off <<= 1) {
            float u0 = __shfl_up_sync(0xFFFFFFFFu, v0, off);
            float u1 = __shfl_up_sync(0xFFFFFFFFu, v1, off);
            if (lane >= off) { v0 = fmaf(pw, u0, v0); v1 = fmaf(pw, u1, v1); }
            pw *= pw;
        }
        const float Dw = pw;                      // a^128
        const float pl = f_ex2(flane4 * lga);     // D^lane

        float* scr = smem + OFF_SCR + bufsel * SCR_SIZE;
        if (lane == 31) { scr[wid] = v0; scr[32 + wid] = v1; }
        if (t == 999)   scr[64] = v0;

        float vex0 = __shfl_up_sync(0xFFFFFFFFu, v0, 1);
        float vex1 = __shfl_up_sync(0xFFFFFFFFu, v1, 1);
        if (lane == 0) { vex0 = 0.0f; vex1 = 0.0f; }

        __syncthreads();                          // the ONLY barrier per row

        // ---- level 3: every warp redundantly scans the 32 warp totals ----
        float w0 = scr[lane], w1 = scr[32 + lane];
        float q  = Dw;
        #pragma unroll
        for (int off = 1; off < 32; off <<= 1) {
            float u0 = __shfl_up_sync(0xFFFFFFFFu, w0, off);
            float u1 = __shfl_up_sync(0xFFFFFFFFu, w1, off);
            if (lane >= off) { w0 = fmaf(q, u0, w0); w1 = fmaf(q, u1, w1); }
            q *= q;
        }

        // chunk-1 seed: n[3999] = D^8 * (state entering warp 31) + val999
        float e31 = __shfl_sync(0xFFFFFFFFu, w0, 30);
        float D2 = D * D, D4 = D2 * D2, D8 = D4 * D4;   // a^32
        const float S0 = fmaf(D8, e31, scr[64]);

        const int src = (wid == 0) ? 0 : (wid - 1);
        float ex0 = __shfl_sync(0xFFFFFFFFu, w0, src);
        float ex1 = __shfl_sync(0xFFFFFFFFu, w1, src);
        if (wid == 0) { ex0 = 0.0f; ex1 = 0.0f; }
        const float plw = f_ex2(fwid128 * lga);   // Dw^wid

        const float carry0 = fmaf(pl, ex0, vex0);
        const float carry1 = fmaf(pl, fmaf(plw, S0, ex1), vex1);

        // ---- pass 2: replay + epilogue, coalesced stores ----
        if (active) {
            float* orow = out + rowoff;
            float n0 = carry0, n1 = carry1;
            #pragma unroll
            for (int i = 0; i < 4; i++) {
                n0 = fmaf(a, n0, (i == 0) ? w00 : c0[i]);
                n1 = fmaf(a, n1, c1[i]);
                float l0 = f_lg2(fmaf(s, n0, EPS_C));
                float l1 = f_lg2(fmaf(s, n1, EPS_C));
                float i0 = f_ex2(-ALPHA_C * l0);
                float i1 = f_ex2(-ALPHA_C * l1);
                float u0 = fmaf(c0[i], i0, DELTA_C);
                float u1 = fmaf(c1[i], i1, DELTA_C);
                c0[i] = f_sqrt(u0) - SQRT_DELTA;
                c1[i] = f_sqrt(u1) - SQRT_DELTA;
            }
            *(float4*)(orow + 4 * t)        = make_float4(c0[0], c0[1], c0[2], c0[3]);
            *(float4*)(orow + HALF + 4 * t) = make_float4(c1[0], c1[1], c1[2], c1[3]);
        }

        // ---- rotate ----
        row = nrow; rowoff = nrowoff; f = nf; s_raw = s_next;
        bufsel ^= 1;
    }
}

extern "C" void kernel_launch(void* const* d_in, const int* in_sizes, int n_in,
                              void* d_out, int out_size)
{
    int xi = 0, si = 1;
    if (n_in >= 2 && in_sizes[0] < in_sizes[1]) { xi = 1; si = 0; }

    const float* x     = (const float*)d_in[xi];
    const float* log_s = (const float*)d_in[si];
    float*       out   = (float*)d_out;

    const int F    = in_sizes[si];           // 128
    const int rows = in_sizes[xi] / TT;      // B*F = 4096

    const int smem_bytes = SMEM_FLOATS * (int)sizeof(float);   // ~64.5 KB
    cudaFuncSetAttribute(pcen_kernel,
                         cudaFuncAttributeMaxDynamicSharedMemorySize, smem_bytes);

    int grid = GRID_MAX; if (grid > rows) grid = rows;
    pcen_kernel<<<grid, NTH, smem_bytes>>>(x, log_s, out, F, rows);
}

// round 12
// speedup vs baseline: 1.2210x; 1.1149x over previous
#include <cuda_runtime.h>
#include <cuda_bf16.h>
#include <cstdint>

// PCEN via exact parallel linear-recurrence scan (constant per-row decay a=1-s).
// R12: persistent kernel, 3-stage cp.async ring (prefetch distance 2,
// wait_group 1 -> newest prefetch stays in flight during compute; DRAM demand
// smoothed), st.global.cs streaming stores (output never re-read; don't thrash
// L2 against prefetch reads). Scan math identical to R9-R11.

#define TT    8000
#define HALF  4000
#define NTH   1024
#define NWARP (NTH/32)
#define GRID_MAX 296            // 2 CTAs/SM * 148 SMs
#define ALPHA_C 0.98f
#define DELTA_C 2.0f
#define EPS_C   1e-6f
#define SQRT_DELTA 1.41421356237f
#define LOG2E 1.44269504089f

// dynamic smem (floats): buf0[8000] buf1[8000] buf2[8000] scr0[66] scr1[66]
#define OFF_SCR   (3*TT)
#define SCR_SIZE  66
#define SMEM_FLOATS (3*TT + 2*SCR_SIZE)

__device__ __forceinline__ float f_lg2(float x) {
    float r; asm("lg2.approx.f32 %0, %1;" : "=f"(r) : "f"(x)); return r;
}
__device__ __forceinline__ float f_ex2(float x) {
    float r; asm("ex2.approx.f32 %0, %1;" : "=f"(r) : "f"(x)); return r;
}
__device__ __forceinline__ float f_sqrt(float x) {
    float r; asm("sqrt.approx.f32 %0, %1;" : "=f"(r) : "f"(x)); return r;
}
__device__ __forceinline__ float f_rcp(float x) {
    float r; asm("rcp.approx.f32 %0, %1;" : "=f"(r) : "f"(x)); return r;
}
__device__ __forceinline__ void cp16(uint32_t saddr, const float* g) {
    asm volatile("cp.async.cg.shared.global [%0], [%1], 16;"
                 :: "r"(saddr), "l"(g));
}
__device__ __forceinline__ void stg_cs(float* g, float a, float b, float c, float d) {
    asm volatile("st.global.cs.v4.f32 [%0], {%1,%2,%3,%4};"
                 :: "l"(g), "f"(a), "f"(b), "f"(c), "f"(d));
}

__global__ __launch_bounds__(NTH, 2)
void pcen_kernel(const float* __restrict__ x,
                 const float* __restrict__ log_s,
                 float* __restrict__ out,
                 int F, int rows)
{
    extern __shared__ float smem[];

    const int t    = threadIdx.x;
    const bool active = (t < HALF / 4);        // threads 0..999
    const int lane = t & 31;
    const int wid  = t >> 5;
    const int stride = gridDim.x;

    const uint32_t sbase = (uint32_t)__cvta_generic_to_shared(smem);
    const uint32_t sA = sbase + 16u * (uint32_t)t;            // half-row slot A
    const uint32_t sB = sA + 4u * HALF;                       // half-row slot B
    const float flane4  = (float)lane * 4.0f;
    const float fwid128 = (float)wid * 128.0f;

    int row = blockIdx.x;
    long long rowoff = (long long)row * TT;
    const long long rowstep = (long long)stride * TT;
    const int fstep = stride % F;

    int f0 = row % F;
    int f1 = f0 + fstep; if (f1 >= F) f1 -= F;
    int f2 = f1 + fstep; if (f2 >= F) f2 -= F;   // index for row + 2*stride

    // s queue: s_cur (row), s_nx1 (row+stride)
    float s_cur = (row < rows) ? __ldg(log_s + f0) : 0.0f;
    float s_nx1 = (row + stride < rows) ? __ldg(log_s + f1) : 0.0f;

    // ---- prologue: prefetch rows r0 -> buf0, r1 -> buf1 ----
    if (row < rows && active) {
        cp16(sA, x + rowoff + 4 * t);
        cp16(sB, x + rowoff + HALF + 4 * t);
    }
    asm volatile("cp.async.commit_group;");
    if (row + stride < rows && active) {
        const long long o1 = rowoff + rowstep;
        const uint32_t b1 = 4u * TT;
        cp16(sA + b1, x + o1 + 4 * t);
        cp16(sB + b1, x + o1 + HALF + 4 * t);
    }
    asm volatile("cp.async.commit_group;");

    int bufsel = 0;       // 0,1,2 ring
    int scrsel = 0;       // 0,1 alternating
    while (row < rows) {
        // ---- current row's copies done; newest prefetch may stay in flight ----
        asm volatile("cp.async.wait_group 1;");

        const uint32_t bofs = (uint32_t)bufsel * (4u * TT);
        float c0[4], c1[4];
        if (active) {
            float4 v0, v1;
            asm volatile("ld.shared.v4.f32 {%0,%1,%2,%3}, [%4];"
                         : "=f"(v0.x), "=f"(v0.y), "=f"(v0.z), "=f"(v0.w)
                         : "r"(sA + bofs));
            asm volatile("ld.shared.v4.f32 {%0,%1,%2,%3}, [%4];"
                         : "=f"(v1.x), "=f"(v1.y), "=f"(v1.z), "=f"(v1.w)
                         : "r"(sB + bofs));
            c0[0]=v0.x; c0[1]=v0.y; c0[2]=v0.z; c0[3]=v0.w;
            c1[0]=v1.x; c1[1]=v1.y; c1[2]=v1.z; c1[3]=v1.w;
        } else {
            #pragma unroll
            for (int i = 0; i < 4; i++) { c0[i] = 0.0f; c1[i] = 0.0f; }
        }

        // ---- issue prefetch for row + 2*stride into the +2 ring slot ----
        const int row2 = row + 2 * stride;
        float s_nx2 = 0.0f;
        {
            int b2 = bufsel + 2; if (b2 >= 3) b2 -= 3;
            const uint32_t nofs = (uint32_t)b2 * (4u * TT);
            if (row2 < rows) {
                s_nx2 = __ldg(log_s + f2);
                const long long o2 = rowoff + 2 * rowstep;
                if (active) {
                    cp16(sA + nofs, x + o2 + 4 * t);
                    cp16(sB + nofs, x + o2 + HALF + 4 * t);
                }
            }
        }
        asm volatile("cp.async.commit_group;");

        // ---- per-row constants ----
        const float s = f_ex2(LOG2E * s_cur);
        const float a = 1.0f - s;
        const float lga = f_lg2(a);
        float a2 = a * a;
        const float D = a2 * a2;                  // a^4 exact

        // init condition folded: n[0] = x0/s -> w00 = x0 * rcp(s) on thread 0
        const float w00 = (t == 0) ? c0[0] * f_rcp(s) : c0[0];

        // ---- pass 1: local n-space scans ----
        float Fv0 = w00, Fv1 = c1[0];
        #pragma unroll
        for (int i = 1; i < 4; i++) {
            Fv0 = fmaf(a, Fv0, c0[i]);
            Fv1 = fmaf(a, Fv1, c1[i]);
        }

        // ---- level 2: fused warp scan ----
        float v0 = Fv0, v1 = Fv1;
        float pw = D;
        #pragma unroll
        for (int off = 1; off < 32; off <<= 1) {
            float u0 = __shfl_up_sync(0xFFFFFFFFu, v0, off);
            float u1 = __shfl_up_sync(0xFFFFFFFFu, v1, off);
            if (lane >= off) { v0 = fmaf(pw, u0, v0); v1 = fmaf(pw, u1, v1); }
            pw *= pw;
        }
        const float Dw = pw;                      // a^128
        const float pl = f_ex2(flane4 * lga);     // D^lane

        float* scr = smem + OFF_SCR + scrsel * SCR_SIZE;
        if (lane == 31) { scr[wid] = v0; scr[32 + wid] = v1; }
        if (t == 999)   scr[64] = v0;

        float vex0 = __shfl_up_sync(0xFFFFFFFFu, v0, 1);
        float vex1 = __shfl_up_sync(0xFFFFFFFFu, v1, 1);
        if (lane == 0) { vex0 = 0.0f; vex1 = 0.0f; }

        __syncthreads();                          // the ONLY barrier per row

        // ---- level 3: every warp redundantly scans the 32 warp totals ----
        float w0 = scr[lane], w1 = scr[32 + lane];
        float q  = Dw;
        #pragma unroll
        for (int off = 1; off < 32; off <<= 1) {
            float u0 = __shfl_up_sync(0xFFFFFFFFu, w0, off);
            float u1 = __shfl_up_sync(0xFFFFFFFFu, w1, off);
            if (lane >= off) { w0 = fmaf(q, u0, w0); w1 = fmaf(q, u1, w1); }
            q *= q;
        }

        // chunk-1 seed: n[3999] = D^8 * (state entering warp 31) + val999
        float e31 = __shfl_sync(0xFFFFFFFFu, w0, 30);
        float D2 = D * D, D4 = D2 * D2, D8 = D4 * D4;   // a^32
        const float S0 = fmaf(D8, e31, scr[64]);

        const int src = (wid == 0) ? 0 : (wid - 1);
        float ex0 = __shfl_sync(0xFFFFFFFFu, w0, src);
        float ex1 = __shfl_sync(0xFFFFFFFFu, w1, src);
        if (wid == 0) { ex0 = 0.0f; ex1 = 0.0f; }
        const float plw = f_ex2(fwid128 * lga);   // Dw^wid

        const float carry0 = fmaf(pl, ex0, vex0);
        const float carry1 = fmaf(pl, fmaf(plw, S0, ex1), vex1);

        // ---- pass 2: replay + epilogue, streaming coalesced stores ----
        if (active) {
            float* orow = out + rowoff;
            float n0 = carry0, n1 = carry1;
            #pragma unroll
            for (int i = 0; i < 4; i++) {
                n0 = fmaf(a, n0, (i == 0) ? w00 : c0[i]);
                n1 = fmaf(a, n1, c1[i]);
                float l0 = f_lg2(fmaf(s, n0, EPS_C));
                float l1 = f_lg2(fmaf(s, n1, EPS_C));
                float i0 = f_ex2(-ALPHA_C * l0);
                float i1 = f_ex2(-ALPHA_C * l1);
                float u0 = fmaf(c0[i], i0, DELTA_C);
                float u1 = fmaf(c1[i], i1, DELTA_C);
                c0[i] = f_sqrt(u0) - SQRT_DELTA;
                c1[i] = f_sqrt(u1) - SQRT_DELTA;
            }
            stg_cs(orow + 4 * t,        c0[0], c0[1], c0[2], c0[3]);
            stg_cs(orow + HALF + 4 * t, c1[0], c1[1], c1[2], c1[3]);
        }

        // ---- rotate ----
        row += stride; rowoff += rowstep;
        s_cur = s_nx1; s_nx1 = s_nx2;
        f2 += fstep; if (f2 >= F) f2 -= F;
        bufsel += 1; if (bufsel >= 3) bufsel = 0;
        scrsel ^= 1;
    }
}

extern "C" void kernel_launch(void* const* d_in, const int* in_sizes, int n_in,
                              void* d_out, int out_size)
{
    int xi = 0, si = 1;
    if (n_in >= 2 && in_sizes[0] < in_sizes[1]) { xi = 1; si = 0; }

    const float* x     = (const float*)d_in[xi];
    const float* log_s = (const float*)d_in[si];
    float*       out   = (float*)d_out;

    const int F    = in_sizes[si];           // 128
    const int rows = in_sizes[xi] / TT;      // B*F = 4096

    const int smem_bytes = SMEM_FLOATS * (int)sizeof(float);   // ~96.5 KB
    cudaFuncSetAttribute(pcen_kernel,
                         cudaFuncAttributeMaxDynamicSharedMemorySize, smem_bytes);

    int grid = GRID_MAX; if (grid > rows) grid = rows;
    pcen_kernel<<<grid, NTH, smem_bytes>>>(x, log_s, out, F, rows);
}

// round 13
// speedup vs baseline: 1.3082x; 1.0715x over previous
#include <cuda_runtime.h>
#include <cuda_bf16.h>
#include <cstdint>

// PCEN via exact parallel linear-recurrence scan (constant per-row decay a=1-s).
// R13: EPT=16 via NTH=512 + 4 chunks of 2000 (amortizes scan machinery over
// 2x elements). One fused level-2 warp scan (4 chains), one 16-wide level-3
// scan, chunk chaining S_{c+1} = T_c + a^2000*S_c with T_c reconstructed via
// the R9 warp-tail method. cp.async 2-buffer pipeline (1 group in flight),
// .cs streaming stores, 1 barrier/row, 3 CTAs/SM.

#define TT     8000
#define CHUNK  2000
#define NTH    512
#define GRID_MAX 444            // 3 CTAs/SM * 148 SMs
#define ALPHA_C 0.98f
#define DELTA_C 2.0f
#define EPS_C   1e-6f
#define SQRT_DELTA 1.41421356237f
#define LOG2E 1.44269504089f

// smem floats: buf[2][8000], scr[2][72]
#define OFF_SCR   (2*TT)
#define SCR_SIZE  72
#define SMEM_FLOATS (2*TT + 2*SCR_SIZE)

__device__ __forceinline__ float f_lg2(float x) {
    float r; asm("lg2.approx.f32 %0, %1;" : "=f"(r) : "f"(x)); return r;
}
__device__ __forceinline__ float f_ex2(float x) {
    float r; asm("ex2.approx.f32 %0, %1;" : "=f"(r) : "f"(x)); return r;
}
__device__ __forceinline__ float f_sqrt(float x) {
    float r; asm("sqrt.approx.f32 %0, %1;" : "=f"(r) : "f"(x)); return r;
}
__device__ __forceinline__ float f_rcp(float x) {
    float r; asm("rcp.approx.f32 %0, %1;" : "=f"(r) : "f"(x)); return r;
}
__device__ __forceinline__ void cp16(uint32_t saddr, const float* g) {
    asm volatile("cp.async.cg.shared.global [%0], [%1], 16;"
                 :: "r"(saddr), "l"(g));
}
__device__ __forceinline__ void stg_cs(float* g, float a, float b, float c, float d) {
    asm volatile("st.global.cs.v4.f32 [%0], {%1,%2,%3,%4};"
                 :: "l"(g), "f"(a), "f"(b), "f"(c), "f"(d));
}
__device__ __forceinline__ float4 lds128(uint32_t saddr) {
    float4 v;
    asm volatile("ld.shared.v4.f32 {%0,%1,%2,%3}, [%4];"
                 : "=f"(v.x), "=f"(v.y), "=f"(v.z), "=f"(v.w) : "r"(saddr));
    return v;
}

__global__ __launch_bounds__(NTH, 3)
void pcen_kernel(const float* __restrict__ x,
                 const float* __restrict__ log_s,
                 float* __restrict__ out,
                 int F, int rows)
{
    extern __shared__ float smem[];

    const int t    = threadIdx.x;
    const bool active = (t < CHUNK / 4);       // threads 0..499
    const int lane = t & 31;
    const int wid  = t >> 5;                   // 0..15
    const int stride = gridDim.x;

    const uint32_t sbase = (uint32_t)__cvta_generic_to_shared(smem);
    const uint32_t sthr  = sbase + 16u * (uint32_t)t;   // thread slot in chunk 0

    int row = blockIdx.x;
    long long rowoff = (long long)row * TT;
    const long long rowstep = (long long)stride * TT;
    int f = row % F;
    const int fstep = stride % F;

    float s_cur = (row < rows) ? __ldg(log_s + f) : 0.0f;

    // ---- prologue: prefetch first row into buf0 (coalesced per chunk) ----
    if (row < rows && active) {
        #pragma unroll
        for (int c = 0; c < 4; c++)
            cp16(sthr + (uint32_t)c * (4u * CHUNK), x + rowoff + c * CHUNK + 4 * t);
    }
    asm volatile("cp.async.commit_group;");

    int bufsel = 0, scrsel = 0;
    while (row < rows) {
        // ---- issue next-row prefetch into the other buffer ----
        const int nrow = row + stride;
        int nf = f + fstep; if (nf >= F) nf -= F;
        float s_nx = 0.0f;
        {
            const uint32_t nb = sthr + (uint32_t)(bufsel ^ 1) * (4u * TT);
            if (nrow < rows) {
                s_nx = __ldg(log_s + nf);
                if (active) {
                    const long long no = rowoff + rowstep;
                    #pragma unroll
                    for (int c = 0; c < 4; c++)
                        cp16(nb + (uint32_t)c * (4u * CHUNK), x + no + c * CHUNK + 4 * t);
                }
            }
        }
        asm volatile("cp.async.commit_group;");
        asm volatile("cp.async.wait_group 1;");   // current done, next in flight

        // ---- per-row constants ----
        const float s = f_ex2(LOG2E * s_cur);
        const float a = 1.0f - s;
        const float lga = f_lg2(a);
        float a2 = a * a;
        const float D = a2 * a2;                  // a^4 exact
        const float rcs = f_rcp(s);

        const uint32_t bb = sthr + (uint32_t)bufsel * (4u * TT);

        // ---- pass 1: local Horner per chunk (data regs transient) ----
        float Fv[4];
        #pragma unroll
        for (int c = 0; c < 4; c++) {
            float4 v = active ? lds128(bb + (uint32_t)c * (4u * CHUNK))
                              : make_float4(0.f, 0.f, 0.f, 0.f);
            float w0 = (t == 0 && c == 0) ? v.x * rcs : v.x;   // fold n[-1]=x0/s
            float Fvc = w0;
            Fvc = fmaf(a, Fvc, v.y);
            Fvc = fmaf(a, Fvc, v.z);
            Fvc = fmaf(a, Fvc, v.w);
            Fv[c] = Fvc;
        }

        // ---- level 2: fused warp scan (4 chains) ----
        float pw = D;
        #pragma unroll
        for (int off = 1; off < 32; off <<= 1) {
            float u0 = __shfl_up_sync(0xFFFFFFFFu, Fv[0], off);
            float u1 = __shfl_up_sync(0xFFFFFFFFu, Fv[1], off);
            float u2 = __shfl_up_sync(0xFFFFFFFFu, Fv[2], off);
            float u3 = __shfl_up_sync(0xFFFFFFFFu, Fv[3], off);
            if (lane >= off) {
                Fv[0] = fmaf(pw, u0, Fv[0]);
                Fv[1] = fmaf(pw, u1, Fv[1]);
                Fv[2] = fmaf(pw, u2, Fv[2]);
                Fv[3] = fmaf(pw, u3, Fv[3]);
            }
            pw *= pw;
        }
        const float Dw = pw;                      // a^128
        const float pl = f_ex2((float)lane * (4.0f * lga));   // D^lane

        float* scr = smem + OFF_SCR + scrsel * SCR_SIZE;
        if (lane == 31) {
            #pragma unroll
            for (int c = 0; c < 4; c++) scr[c * 16 + wid] = Fv[c];
        }
        if (t == 499) {
            #pragma unroll
            for (int c = 0; c < 4; c++) scr[64 + c] = Fv[c];   // lane-19 partials
        }

        float vex[4];
        #pragma unroll
        for (int c = 0; c < 4; c++) {
            vex[c] = __shfl_up_sync(0xFFFFFFFFu, Fv[c], 1);
            if (lane == 0) vex[c] = 0.0f;
        }

        __syncthreads();                          // the ONLY barrier per row

        // ---- level 3: 16-wide scan of warp totals (all warps redundant) ----
        float w[4];
        {
            const int ln = lane & 15;
            #pragma unroll
            for (int c = 0; c < 4; c++) w[c] = scr[c * 16 + ln];
        }
        float q = Dw;
        #pragma unroll
        for (int off = 1; off < 16; off <<= 1) {
            float u0 = __shfl_up_sync(0xFFFFFFFFu, w[0], off);
            float u1 = __shfl_up_sync(0xFFFFFFFFu, w[1], off);
            float u2 = __shfl_up_sync(0xFFFFFFFFu, w[2], off);
            float u3 = __shfl_up_sync(0xFFFFFFFFu, w[3], off);
            if (lane >= off) {
                w[0] = fmaf(q, u0, w[0]);
                w[1] = fmaf(q, u1, w[1]);
                w[2] = fmaf(q, u2, w[2]);
                w[3] = fmaf(q, u3, w[3]);
            }
            q *= q;
        }

        // chunk totals: T_c = a^80 * (state through warp 14) + thread499 partial
        const float a80 = f_ex2(80.0f * lga);
        float T0, T1, T2;
        {
            float e0 = __shfl_sync(0xFFFFFFFFu, w[0], 14);
            float e1 = __shfl_sync(0xFFFFFFFFu, w[1], 14);
            float e2 = __shfl_sync(0xFFFFFFFFu, w[2], 14);
            T0 = fmaf(a80, e0, scr[64]);
            T1 = fmaf(a80, e1, scr[65]);
            T2 = fmaf(a80, e2, scr[66]);
        }
        // chunk seeds (exact chaining; az ~ 1e-32 for this data but kept exact)
        const float az = f_ex2(2000.0f * lga);
        const float S1 = T0;
        const float S2 = fmaf(az, S1, T1);
        const float S3 = fmaf(az, S2, T2);

        // exclusive level-3 prefixes for this warp
        const int src = (wid == 0) ? 0 : (wid - 1);
        float ex[4];
        #pragma unroll
        for (int c = 0; c < 4; c++) {
            ex[c] = __shfl_sync(0xFFFFFFFFu, w[c], src);
            if (wid == 0) ex[c] = 0.0f;
        }
        const float plw = f_ex2((float)wid * (128.0f * lga));  // Dw^wid

        float carry[4];
        carry[0] = fmaf(pl, ex[0], vex[0]);
        carry[1] = fmaf(pl, fmaf(plw, S1, ex[1]), vex[1]);
        carry[2] = fmaf(pl, fmaf(plw, S2, ex[2]), vex[2]);
        carry[3] = fmaf(pl, fmaf(plw, S3, ex[3]), vex[3]);

        // ---- pass 2: re-read buffer, replay + epilogue, coalesced .cs stores ----
        if (active) {
            float* orow = out + rowoff;
            #pragma unroll
            for (int c = 0; c < 4; c++) {
                float4 v = lds128(bb + (uint32_t)c * (4u * CHUNK));
                float w0 = (t == 0 && c == 0) ? v.x * rcs : v.x;
                float n = carry[c];
                float o0, o1, o2, o3;
                n = fmaf(a, n, w0);
                { float l = f_lg2(fmaf(s, n, EPS_C));
                  float p = f_ex2(-ALPHA_C * l);
                  o0 = f_sqrt(fmaf(v.x, p, DELTA_C)) - SQRT_DELTA; }
                n = fmaf(a, n, v.y);
                { float l = f_lg2(fmaf(s, n, EPS_C));
                  float p = f_ex2(-ALPHA_C * l);
                  o1 = f_sqrt(fmaf(v.y, p, DELTA_C)) - SQRT_DELTA; }
                n = fmaf(a, n, v.z);
                { float l = f_lg2(fmaf(s, n, EPS_C));
                  float p = f_ex2(-ALPHA_C * l);
                  o2 = f_sqrt(fmaf(v.z, p, DELTA_C)) - SQRT_DELTA; }
                n = fmaf(a, n, v.w);
                { float l = f_lg2(fmaf(s, n, EPS_C));
                  float p = f_ex2(-ALPHA_C * l);
                  o3 = f_sqrt(fmaf(v.w, p, DELTA_C)) - SQRT_DELTA; }
                stg_cs(orow + c * CHUNK + 4 * t, o0, o1, o2, o3);
            }
        }

        // ---- rotate ----
        row = nrow; rowoff += rowstep; f = nf; s_cur = s_nx;
        bufsel ^= 1; scrsel ^= 1;
    }
}

extern "C" void kernel_launch(void* const* d_in, const int* in_sizes, int n_in,
                              void* d_out, int out_size)
{
    int xi = 0, si = 1;
    if (n_in >= 2 && in_sizes[0] < in_sizes[1]) { xi = 1; si = 0; }

    const float* x     = (const float*)d_in[xi];
    const float* log_s = (const float*)d_in[si];
    float*       out   = (float*)d_out;

    const int F    = in_sizes[si];           // 128
    const int rows = in_sizes[xi] / TT;      // B*F = 4096

    const int smem_bytes = SMEM_FLOATS * (int)sizeof(float);   // ~64.6 KB
    cudaFuncSetAttribute(pcen_kernel,
                         cudaFuncAttributeMaxDynamicSharedMemorySize, smem_bytes);

    int grid = GRID_MAX; if (grid > rows) grid = rows;
    pcen_kernel<<<grid, NTH, smem_bytes>>>(x, log_s, out, F, rows);
}

// round 14
// speedup vs baseline: 1.3209x; 1.0097x over previous
#include <cuda_runtime.h>
#include <cuda_bf16.h>
#include <cstdint>

// PCEN via exact parallel linear-recurrence scan (constant per-row decay a=1-s).
// R14: R13 compute core + DYNAMIC row scheduling (global atomic work queue,
// reset by an init kernel each launch). Thread0 grabs the next row pre-barrier,
// publishes via the scr double-buffer; all threads issue its prefetch right
// after the barrier (window = level3 + pass2). Removes the 10-vs-9 rows/CTA
// static-stride tail (~8%). row%F -> row&(F-1) for power-of-two F.

#define TT     8000
#define CHUNK  2000
#define NTH    512
#define GRID_MAX 444            // 3 CTAs/SM * 148 SMs
#define ALPHA_C 0.98f
#define DELTA_C 2.0f
#define EPS_C   1e-6f
#define SQRT_DELTA 1.41421356237f
#define LOG2E 1.44269504089f

// smem floats: buf[2][8000], scr[2][72]
// scr layout: [0..63] warp totals (4 chunks x 16), [64..67] t499 partials,
//             [68] next-row mailbox (int bits)
#define OFF_SCR   (2*TT)
#define SCR_SIZE  72
#define SMEM_FLOATS (2*TT + 2*SCR_SIZE)

__device__ int g_next_row;

__global__ void pcen_init() { g_next_row = 0; }

__device__ __forceinline__ float f_lg2(float x) {
    float r; asm("lg2.approx.f32 %0, %1;" : "=f"(r) : "f"(x)); return r;
}
__device__ __forceinline__ float f_ex2(float x) {
    float r; asm("ex2.approx.f32 %0, %1;" : "=f"(r) : "f"(x)); return r;
}
__device__ __forceinline__ float f_sqrt(float x) {
    float r; asm("sqrt.approx.f32 %0, %1;" : "=f"(r) : "f"(x)); return r;
}
__device__ __forceinline__ float f_rcp(float x) {
    float r; asm("rcp.approx.f32 %0, %1;" : "=f"(r) : "f"(x)); return r;
}
__device__ __forceinline__ void cp16(uint32_t saddr, const float* g) {
    asm volatile("cp.async.cg.shared.global [%0], [%1], 16;"
                 :: "r"(saddr), "l"(g));
}
__device__ __forceinline__ void stg_cs(float* g, float a, float b, float c, float d) {
    asm volatile("st.global.cs.v4.f32 [%0], {%1,%2,%3,%4};"
                 :: "l"(g), "f"(a), "f"(b), "f"(c), "f"(d));
}
__device__ __forceinline__ float4 lds128(uint32_t saddr) {
    float4 v;
    asm volatile("ld.shared.v4.f32 {%0,%1,%2,%3}, [%4];"
                 : "=f"(v.x), "=f"(v.y), "=f"(v.z), "=f"(v.w) : "r"(saddr));
    return v;
}

__global__ __launch_bounds__(NTH, 3)
void pcen_kernel(const float* __restrict__ x,
                 const float* __restrict__ log_s,
                 float* __restrict__ out,
                 int F, int Fmask, int rows)
{
    extern __shared__ float smem[];

    const int t    = threadIdx.x;
    const bool active = (t < CHUNK / 4);       // threads 0..499
    const int lane = t & 31;
    const int wid  = t >> 5;                   // 0..15

    const uint32_t sbase = (uint32_t)__cvta_generic_to_shared(smem);
    const uint32_t sthr  = sbase + 16u * (uint32_t)t;

    // ---- prologue: grab first row, prefetch, load its s ----
    if (t == 0) {
        int r0 = atomicAdd(&g_next_row, 1);
        smem[OFF_SCR + 68] = __int_as_float(r0);
    }
    __syncthreads();
    int row = __float_as_int(smem[OFF_SCR + 68]);

    float s_cur = 0.0f;
    if (row < rows) {
        int f0 = (Fmask >= 0) ? (row & Fmask) : (row % F);
        s_cur = __ldg(log_s + f0);
        if (active) {
            const long long o = (long long)row * TT;
            #pragma unroll
            for (int c = 0; c < 4; c++)
                cp16(sthr + (uint32_t)c * (4u * CHUNK), x + o + c * CHUNK + 4 * t);
        }
    }
    asm volatile("cp.async.commit_group;");

    int bufsel = 0, scrsel = 0;
    while (row < rows) {
        asm volatile("cp.async.wait_group 0;");   // this row's data ready

        // ---- per-row constants ----
        const float s = f_ex2(LOG2E * s_cur);
        const float a = 1.0f - s;
        const float lga = f_lg2(a);
        float a2 = a * a;
        const float D = a2 * a2;                  // a^4 exact
        const float rcs = f_rcp(s);

        const uint32_t bb = sthr + (uint32_t)bufsel * (4u * TT);
        float* scr = smem + OFF_SCR + scrsel * SCR_SIZE;

        // ---- pass 1: local Horner per chunk ----
        float Fv[4];
        #pragma unroll
        for (int c = 0; c < 4; c++) {
            float4 v = active ? lds128(bb + (uint32_t)c * (4u * CHUNK))
                              : make_float4(0.f, 0.f, 0.f, 0.f);
            float w0 = (t == 0 && c == 0) ? v.x * rcs : v.x;   // fold n[-1]=x0/s
            float Fvc = w0;
            Fvc = fmaf(a, Fvc, v.y);
            Fvc = fmaf(a, Fvc, v.z);
            Fvc = fmaf(a, Fvc, v.w);
            Fv[c] = Fvc;
        }

        // ---- level 2: fused warp scan (4 chains) ----
        float pw = D;
        #pragma unroll
        for (int off = 1; off < 32; off <<= 1) {
            float u0 = __shfl_up_sync(0xFFFFFFFFu, Fv[0], off);
            float u1 = __shfl_up_sync(0xFFFFFFFFu, Fv[1], off);
            float u2 = __shfl_up_sync(0xFFFFFFFFu, Fv[2], off);
            float u3 = __shfl_up_sync(0xFFFFFFFFu, Fv[3], off);
            if (lane >= off) {
                Fv[0] = fmaf(pw, u0, Fv[0]);
                Fv[1] = fmaf(pw, u1, Fv[1]);
                Fv[2] = fmaf(pw, u2, Fv[2]);
                Fv[3] = fmaf(pw, u3, Fv[3]);
            }
            pw *= pw;
        }
        const float Dw = pw;                      // a^128
        const float pl = f_ex2((float)lane * (4.0f * lga));   // D^lane

        if (lane == 31) {
            #pragma unroll
            for (int c = 0; c < 4; c++) scr[c * 16 + wid] = Fv[c];
        }
        if (t == 499) {
            #pragma unroll
            for (int c = 0; c < 4; c++) scr[64 + c] = Fv[c];
        }

        // ---- grab next row (pre-barrier publish) ----
        if (t == 0) {
            int nr = atomicAdd(&g_next_row, 1);
            scr[68] = __int_as_float(nr);
        }

        float vex[4];
        #pragma unroll
        for (int c = 0; c < 4; c++) {
            vex[c] = __shfl_up_sync(0xFFFFFFFFu, Fv[c], 1);
            if (lane == 0) vex[c] = 0.0f;
        }

        __syncthreads();                          // the ONLY barrier per row

        // ---- read next row, issue its prefetch NOW (window: level3+pass2) ----
        const int nrow = __float_as_int(scr[68]);
        float s_nx = 0.0f;
        if (nrow < rows) {
            int nf = (Fmask >= 0) ? (nrow & Fmask) : (nrow % F);
            s_nx = __ldg(log_s + nf);
            if (active) {
                const long long no = (long long)nrow * TT;
                const uint32_t nb = sthr + (uint32_t)(bufsel ^ 1) * (4u * TT);
                #pragma unroll
                for (int c = 0; c < 4; c++)
                    cp16(nb + (uint32_t)c * (4u * CHUNK), x + no + c * CHUNK + 4 * t);
            }
        }
        asm volatile("cp.async.commit_group;");

        // ---- level 3: 16-wide scan of warp totals (all warps redundant) ----
        float w[4];
        {
            const int ln = lane & 15;
            #pragma unroll
            for (int c = 0; c < 4; c++) w[c] = scr[c * 16 + ln];
        }
        float q = Dw;
        #pragma unroll
        for (int off = 1; off < 16; off <<= 1) {
            float u0 = __shfl_up_sync(0xFFFFFFFFu, w[0], off);
            float u1 = __shfl_up_sync(0xFFFFFFFFu, w[1], off);
            float u2 = __shfl_up_sync(0xFFFFFFFFu, w[2], off);
            float u3 = __shfl_up_sync(0xFFFFFFFFu, w[3], off);
            if (lane >= off) {
                w[0] = fmaf(q, u0, w[0]);
                w[1] = fmaf(q, u1, w[1]);
                w[2] = fmaf(q, u2, w[2]);
                w[3] = fmaf(q, u3, w[3]);
            }
            q *= q;
        }

        // chunk totals: T_c = a^80 * (state through warp 14) + thread499 partial
        const float a80 = f_ex2(80.0f * lga);
        float T0, T1, T2;
        {
            float e0 = __shfl_sync(0xFFFFFFFFu, w[0], 14);
            float e1 = __shfl_sync(0xFFFFFFFFu, w[1], 14);
            float e2 = __shfl_sync(0xFFFFFFFFu, w[2], 14);
            T0 = fmaf(a80, e0, scr[64]);
            T1 = fmaf(a80, e1, scr[65]);
            T2 = fmaf(a80, e2, scr[66]);
        }
        const float az = f_ex2(2000.0f * lga);
        const float S1 = T0;
        const float S2 = fmaf(az, S1, T1);
        const float S3 = fmaf(az, S2, T2);

        const int src = (wid == 0) ? 0 : (wid - 1);
        float ex[4];
        #pragma unroll
        for (int c = 0; c < 4; c++) {
            ex[c] = __shfl_sync(0xFFFFFFFFu, w[c], src);
            if (wid == 0) ex[c] = 0.0f;
        }
        const float plw = f_ex2((float)wid * (128.0f * lga));  // Dw^wid

        float carry[4];
        carry[0] = fmaf(pl, ex[0], vex[0]);
        carry[1] = fmaf(pl, fmaf(plw, S1, ex[1]), vex[1]);
        carry[2] = fmaf(pl, fmaf(plw, S2, ex[2]), vex[2]);
        carry[3] = fmaf(pl, fmaf(plw, S3, ex[3]), vex[3]);

        // ---- pass 2: re-read buffer, replay + epilogue, .cs stores ----
        if (active) {
            float* orow = out + (long long)row * TT;
            #pragma unroll
            for (int c = 0; c < 4; c++) {
                float4 v = lds128(bb + (uint32_t)c * (4u * CHUNK));
                float w0 = (t == 0 && c == 0) ? v.x * rcs : v.x;
                float n = carry[c];
                float o0, o1, o2, o3;
                n = fmaf(a, n, w0);
                { float l = f_lg2(fmaf(s, n, EPS_C));
                  float p = f_ex2(-ALPHA_C * l);
                  o0 = f_sqrt(fmaf(v.x, p, DELTA_C)) - SQRT_DELTA; }
                n = fmaf(a, n, v.y);
                { float l = f_lg2(fmaf(s, n, EPS_C));
                  float p = f_ex2(-ALPHA_C * l);
                  o1 = f_sqrt(fmaf(v.y, p, DELTA_C)) - SQRT_DELTA; }
                n = fmaf(a, n, v.z);
                { float l = f_lg2(fmaf(s, n, EPS_C));
                  float p = f_ex2(-ALPHA_C * l);
                  o2 = f_sqrt(fmaf(v.z, p, DELTA_C)) - SQRT_DELTA; }
                n = fmaf(a, n, v.w);
                { float l = f_lg2(fmaf(s, n, EPS_C));
                  float p = f_ex2(-ALPHA_C * l);
                  o3 = f_sqrt(fmaf(v.w, p, DELTA_C)) - SQRT_DELTA; }
                stg_cs(orow + c * CHUNK + 4 * t, o0, o1, o2, o3);
            }
        }

        // ---- rotate ----
        row = nrow; s_cur = s_nx;
        bufsel ^= 1; scrsel ^= 1;
    }
}

extern "C" void kernel_launch(void* const* d_in, const int* in_sizes, int n_in,
                              void* d_out, int out_size)
{
    int xi = 0, si = 1;
    if (n_in >= 2 && in_sizes[0] < in_sizes[1]) { xi = 1; si = 0; }

    const float* x     = (const float*)d_in[xi];
    const float* log_s = (const float*)d_in[si];
    float*       out   = (float*)d_out;

    const int F    = in_sizes[si];           // 128
    const int rows = in_sizes[xi] / TT;      // B*F = 4096
    const int Fmask = ((F & (F - 1)) == 0) ? (F - 1) : -1;

    const int smem_bytes = SMEM_FLOATS * (int)sizeof(float);   // ~64.6 KB
    cudaFuncSetAttribute(pcen_kernel,
                         cudaFuncAttributeMaxDynamicSharedMemorySize, smem_bytes);

    pcen_init<<<1, 1>>>();
    int grid = GRID_MAX; if (grid > rows) grid = rows;
    pcen_kernel<<<grid, NTH, smem_bytes>>>(x, log_s, out, F, Fmask, rows);
}